// round 11
// baseline (speedup 1.0000x reference)
#include <cuda_runtime.h>
#include <cuda_fp16.h>
#include <cstdint>

// ---------------- problem constants ----------------
#define BATCH   4
#define CIN     128
#define COUT    128
#define HDIM    128
#define WDIM    128
#define HW      (HDIM * WDIM)      // 16384
#define NGROUP  4
#define CG      32
#define KTAPS   9
#define RTOT    (CIN * KTAPS)      // 1152 = 72 * 16
#define NSTEP   72                 // k16 steps
#define TPX     32                 // pixels (N) per block
#define NTHREADS 256

// ---------------- smem layout (bytes) ----------------
// S (samples, f16): [1152 k][64 B swizzled row] = 73728
// misc @ 73728: ss0(128), ss1(128), swo(576)
#define SMEM_S_OFF   0
#define SMEM_MISC    73728
#define OFF_SS0      (SMEM_MISC + 0)
#define OFF_SS1      (SMEM_MISC + 128)
#define OFF_SWO      (SMEM_MISC + 256)
#define SMEM_BYTES   (SMEM_MISC + 832)   // 74560  (x3 CTAs = 223,680)

// k-row permutation: k = gk*32 + cg  (gk = g*9+tap in [0,36), cg in [0,32))
// swizzle: chunk ^= ((k>>1)^(k>>3))&3  — conflict-free for both the
// oct-strided sample STS (k stride 8 -> (k>>3) spreads) and ldmatrix's
// 8-consecutive-row phases ((k>>1) spreads pairs; (k>>3) constant).
#define SWZK(k) ((((k) >> 1) ^ ((k) >> 3)) & 3)

// Weights pre-packed in m16n8k16 A-fragment order (k-permuted to match S):
// uint4 idx = (step*8 + otile)*32 + lane
__device__ __align__(16) uint32_t g_wAf32[NSTEP * 8 * 32 * 4];   // 294912 B

// Channel-last f16 copy of x: [B][G][HW][32ch] as u32 pairs (16 u32 / spatial)
__device__ __align__(16) uint32_t g_xt32[BATCH * NGROUP * HW * 16];  // 16 MB

__device__ __forceinline__ uint32_t smem_to_u32(const void* p) {
    uint32_t a;
    asm("{ .reg .u64 t; cvta.to.shared.u64 t, %1; cvt.u32.u64 %0, t; }" : "=r"(a) : "l"(p));
    return a;
}

__device__ __forceinline__ int s_off(int k, int px) {
    return (k << 6) + ((px & 7) << 1) + ((((px >> 3) ^ SWZK(k))) << 4);
}

__device__ __forceinline__ void ldsm_x4_trans(uint32_t* r, uint32_t addr) {
    asm volatile("ldmatrix.sync.aligned.m8n8.x4.trans.shared.b16 {%0,%1,%2,%3}, [%4];"
                 : "=r"(r[0]), "=r"(r[1]), "=r"(r[2]), "=r"(r[3]) : "r"(addr));
}
__device__ __forceinline__ void mma_f16(float* c, const uint32_t* a, uint32_t b0, uint32_t b1) {
    asm volatile(
        "mma.sync.aligned.m16n8k16.row.col.f32.f16.f16.f32 "
        "{%0,%1,%2,%3}, {%4,%5,%6,%7}, {%8,%9}, {%0,%1,%2,%3};"
        : "+f"(c[0]), "+f"(c[1]), "+f"(c[2]), "+f"(c[3])
        : "r"(a[0]), "r"(a[1]), "r"(a[2]), "r"(a[3]), "r"(b0), "r"(b1));
}

__device__ __forceinline__ float2 h2_to_f2(uint32_t u) {
    __half2 h = *reinterpret_cast<__half2*>(&u);
    return __half22float2(h);
}

// ---------------- prep 1: x -> channel-last f16 (smem-tiled transpose) -------
// block: one (b, g, 256-spatial slab). 1024 blocks x 256 threads.
__global__ void prep_xt_kernel(const float* __restrict__ x) {
    __shared__ uint32_t tile[16][257];    // [ch-pair][s] packed half2
    const int t   = threadIdx.x;
    const int sb  = blockIdx.x & 63;
    const int bg  = blockIdx.x >> 6;      // b*4 + g
    const int s0  = sb << 8;
    const float* xb = x + (size_t)bg * 32 * HW + s0;
    #pragma unroll
    for (int k = 0; k < 16; k++) {
        float a  = xb[(size_t)(2*k)   * HW + t];
        float bb = xb[(size_t)(2*k+1) * HW + t];
        __half2 h = __floats2half2_rn(a, bb);
        tile[k][t] = *reinterpret_cast<uint32_t*>(&h);
    }
    __syncthreads();
    uint32_t* outp = g_xt32 + ((size_t)bg * HW + s0) * 16;
    #pragma unroll
    for (int q = 0; q < 16; q++) {
        int idx = (q << 8) + t;
        outp[idx] = tile[idx & 15][idx >> 4];
    }
}

// ---------------- prep 2: weights -> A-fragment layout, f16, k-permuted ------
__global__ void prep_wAf_kernel(const float* __restrict__ wd) {
    int idx = blockIdx.x * 256 + threadIdx.x;       // b32 index
    if (idx >= NSTEP * 8 * 32 * 4) return;
    int q     = idx & 3;
    int lane  = (idx >> 2) & 31;
    int ot    = (idx >> 7) & 7;
    int step  = idx >> 10;
    int g = lane >> 2, t = lane & 3;
    int row = ot * 16 + g + ((q & 1) << 3);
    int col0 = step * 16 + t * 2 + ((q >> 1) << 3);
    // permuted k -> original weight column: k = gk*32+cg -> (grp*32+cg)*9+tap
    auto wmap = [&](int k) -> float {
        int cg = k & 31, gk = k >> 5;
        int grp = gk / 9, tap = gk - grp * 9;
        return wd[row * RTOT + (grp * 32 + cg) * KTAPS + tap];
    };
    __half h0 = __float2half_rn(wmap(col0));
    __half h1 = __float2half_rn(wmap(col0 + 1));
    g_wAf32[idx] = ((uint32_t)reinterpret_cast<unsigned short&>(h1) << 16)
                 |  (uint32_t)reinterpret_cast<unsigned short&>(h0);
}

// ---------------- main kernel ----------------
__global__ void __launch_bounds__(NTHREADS, 3)
deform_kernel(const float* __restrict__ x,        // [B,C,H,W] (unused; via g_xt32)
              const float* __restrict__ shape,    // [B,2,H,W]
              const float* __restrict__ w_offset, // [72][2]
              float* __restrict__ out)            // [B,COUT,H,W]
{
    extern __shared__ char smem[];
    const uint32_t smem_u32 = smem_to_u32(smem);
    float* ss0 = (float*)(smem + OFF_SS0);
    float* ss1 = (float*)(smem + OFF_SS1);
    float* swo = (float*)(smem + OFF_SWO);

    const int tid = threadIdx.x;
    const int wid = tid >> 5;
    const int lid = tid & 31;

    const int b   = blockIdx.x >> 9;
    const int rem = blockIdx.x & 511;
    const int h   = rem >> 2;
    const int w0  = (rem & 3) << 5;

    // ---- stage small tables ----
    if (tid < 32)                     ss0[tid]     = shape[(size_t)(b*2+0)*HW + h*WDIM + w0 + tid];
    else if (tid < 64)                ss1[tid-32]  = shape[(size_t)(b*2+1)*HW + h*WDIM + w0 + (tid-32)];
    else if (tid >= 64 && tid < 208)  swo[tid-64]  = w_offset[tid-64];
    __syncthreads();

    // ---- phase A: vectorized gather from channel-last xt ----
    // pass = (gk, px-block p); lane = (oct in [0,4), px8 in [0,8))
    {
        const int oct = lid >> 3, px8 = lid & 7;
        for (int P = wid; P < 36 * 4; P += 8) {
            const int gk = P >> 2, p = P & 3;
            const int px = (p << 3) + px8;
            const int g  = gk / 9, tap = gk - g * 9;
            const int ky = tap / 3, kx = tap - ky * 3;
            float s0 = ss0[px], s1 = ss1[px];
            float offy = swo[gk*4 + 0] * s0 + swo[gk*4 + 1] * s1;
            float offx = swo[gk*4 + 2] * s0 + swo[gk*4 + 3] * s1;
            float py  = offy + (float)(ky - 1 + h);
            float pxf = offx + (float)(kx - 1 + w0 + px);
            float y0f = floorf(py), x0f = floorf(pxf);
            float fy = py - y0f, fx = pxf - x0f;
            int y0 = (int)y0f, x0 = (int)x0f;

            float aw[4]; int ai[4];
            #pragma unroll
            for (int t = 0; t < 4; t++) {
                int dy = t >> 1, dx = t & 1;
                int yi = y0 + dy, xi = x0 + dx;
                bool valid = (yi >= 0) && (yi < HDIM) && (xi >= 0) && (xi < WDIM);
                float wy = dy ? fy : 1.0f - fy;
                float wx = dx ? fx : 1.0f - fx;
                int yc = min(max(yi, 0), HDIM - 1);
                int xc = min(max(xi, 0), WDIM - 1);
                aw[t] = valid ? (wy * wx) : 0.0f;
                ai[t] = yc * WDIM + xc;
            }

            // 4 corner loads: 8 channels (oct*8..+7) each, 16B
            const uint4* xtb =
                reinterpret_cast<const uint4*>(g_xt32) +
                ((size_t)(b * NGROUP + g) * HW) * 4 + oct;
            uint4 c0 = xtb[(size_t)ai[0] * 4];
            uint4 c1 = xtb[(size_t)ai[1] * 4];
            uint4 c2 = xtb[(size_t)ai[2] * 4];
            uint4 c3 = xtb[(size_t)ai[3] * 4];

            const int r0 = (gk << 5) + (oct << 3);   // first of 8 k-rows
            const uint32_t* u0 = (const uint32_t*)&c0;
            const uint32_t* u1 = (const uint32_t*)&c1;
            const uint32_t* u2 = (const uint32_t*)&c2;
            const uint32_t* u3 = (const uint32_t*)&c3;
            #pragma unroll
            for (int j = 0; j < 4; j++) {
                float2 f0 = h2_to_f2(u0[j]), f1 = h2_to_f2(u1[j]);
                float2 f2 = h2_to_f2(u2[j]), f3 = h2_to_f2(u3[j]);
                float vlo = aw[0]*f0.x + aw[1]*f1.x + aw[2]*f2.x + aw[3]*f3.x;
                float vhi = aw[0]*f0.y + aw[1]*f1.y + aw[2]*f2.y + aw[3]*f3.y;
                __half2 hv = __floats2half2_rn(vlo, vhi);
                int r = r0 + 2*j;
                *(__half*)(smem + SMEM_S_OFF + s_off(r,     px)) = __low2half(hv);
                *(__half*)(smem + SMEM_S_OFF + s_off(r + 1, px)) = __high2half(hv);
            }
        }
    }
    __syncthreads();

    // ---- phase B: 8 warps, each o16 x n32 over full k ----
    const int ot    = wid;               // o = wid*16 .. +15
    const int bkrow = lid & 15;
    const int bsel  = lid >> 4;

    const uint4* gA = reinterpret_cast<const uint4*>(g_wAf32);

    float acc[4][4];
    #pragma unroll
    for (int a2 = 0; a2 < 4; a2++)
        #pragma unroll
        for (int a3 = 0; a3 < 4; a3++) acc[a2][a3] = 0.0f;

    uint4 curA = gA[((0*8 + ot) << 5) + lid];

    for (int step = 0; step < NSTEP; step++) {
        uint4 nxtA;
        if (step + 1 < NSTEP)
            nxtA = gA[(((step+1)*8 + ot) << 5) + lid];

        const int k = (step << 4) + bkrow;
        uint32_t bf[2][4];
        #pragma unroll
        for (int half = 0; half < 2; half++) {
            int bnchk = (half << 1) + bsel;
            int boff  = (k << 6) + (((bnchk ^ SWZK(k))) << 4);
            ldsm_x4_trans(bf[half], smem_u32 + SMEM_S_OFF + (uint32_t)boff);
        }

        const uint32_t* a = (const uint32_t*)&curA;
        mma_f16(acc[0], a, bf[0][0], bf[0][1]);
        mma_f16(acc[1], a, bf[0][2], bf[0][3]);
        mma_f16(acc[2], a, bf[1][0], bf[1][1]);
        mma_f16(acc[3], a, bf[1][2], bf[1][3]);

        curA = nxtA;
    }

    // ---- epilogue: acc -> ReLU -> gmem ----
    const int g = lid >> 2, t = lid & 3;
    #pragma unroll
    for (int j = 0; j < 4; j++) {
        int o  = (wid << 4) + g;
        int px = (j << 3) + (t << 1);
        float* op0 = out + (((size_t)b * COUT + o) << 14) + (h << 7) + w0 + px;
        float* op1 = op0 + ((size_t)8 << 14);   // row o+8
        float2 v0 = { fmaxf(acc[j][0], 0.0f), fmaxf(acc[j][1], 0.0f) };
        float2 v1 = { fmaxf(acc[j][2], 0.0f), fmaxf(acc[j][3], 0.0f) };
        *reinterpret_cast<float2*>(op0) = v0;
        *reinterpret_cast<float2*>(op1) = v1;
    }
}

extern "C" void kernel_launch(void* const* d_in, const int* in_sizes, int n_in,
                              void* d_out, int out_size) {
    const float* x        = (const float*)d_in[0];
    const float* shape    = (const float*)d_in[1];
    const float* w_offset = (const float*)d_in[2];
    const float* w_deform = (const float*)d_in[3];
    float* out = (float*)d_out;

    cudaFuncSetAttribute(deform_kernel,
                         cudaFuncAttributeMaxDynamicSharedMemorySize, SMEM_BYTES);

    prep_xt_kernel<<<BATCH * NGROUP * (HW / 256), 256>>>(x);
    prep_wAf_kernel<<<(NSTEP * 8 * 32 * 4 + 255) / 256, 256>>>(w_deform);

    const int nblocks = BATCH * HDIM * (WDIM / TPX);   // 2048
    deform_kernel<<<nblocks, NTHREADS, SMEM_BYTES>>>(x, shape, w_offset, out);
}

// round 12
// speedup vs baseline: 1.1114x; 1.1114x over previous
#include <cuda_runtime.h>
#include <cuda_fp16.h>
#include <cstdint>

// ---------------- problem constants ----------------
#define BATCH   4
#define CIN     128
#define COUT    128
#define HDIM    128
#define WDIM    128
#define HW      (HDIM * WDIM)      // 16384
#define NGROUP  4
#define CG      32
#define KTAPS   9
#define RTOT    (CIN * KTAPS)      // 1152 = 72 * 16
#define NSTEP   72                 // k16 steps
#define TPX     32                 // pixels (N) per block
#define NTHREADS 256

// ---------------- smem layout (bytes) ----------------
// S (samples, f16 single plane): [1152 k][64 B swizzled row] = 73728
// misc @ 73728: ss0(128), ss1(128), swo(576)
#define SMEM_S_OFF   0
#define SMEM_MISC    73728
#define OFF_SS0      (SMEM_MISC + 0)
#define OFF_SS1      (SMEM_MISC + 128)
#define OFF_SWO      (SMEM_MISC + 256)
#define SMEM_BYTES   (SMEM_MISC + 832)   // 74560  (x3 CTAs = 223,680)

// Weights pre-packed in m16n8k16 A-fragment order, single f16 plane:
// uint4 idx = (step*8 + otile)*32 + lane
__device__ __align__(16) uint32_t g_wAf32[NSTEP * 8 * 32 * 4];   // 294912 B

__device__ __forceinline__ uint32_t smem_to_u32(const void* p) {
    uint32_t a;
    asm("{ .reg .u64 t; cvta.to.shared.u64 t, %1; cvt.u32.u64 %0, t; }" : "=r"(a) : "l"(p));
    return a;
}

// S swizzle: row k is 64B (32 px f16), 4 x 16B chunks; chunk ^= (k>>1)&3 so
// ldmatrix's 8-row phases hit disjoint 16B groups.
__device__ __forceinline__ int s_off(int k, int px) {
    return (k << 6) + ((px & 7) << 1) + ((((px >> 3) ^ ((k >> 1) & 3))) << 4);
}

__device__ __forceinline__ void ldsm_x4_trans(uint32_t* r, uint32_t addr) {
    asm volatile("ldmatrix.sync.aligned.m8n8.x4.trans.shared.b16 {%0,%1,%2,%3}, [%4];"
                 : "=r"(r[0]), "=r"(r[1]), "=r"(r[2]), "=r"(r[3]) : "r"(addr));
}
__device__ __forceinline__ void mma_f16(float* c, const uint32_t* a, uint32_t b0, uint32_t b1) {
    asm volatile(
        "mma.sync.aligned.m16n8k16.row.col.f32.f16.f16.f32 "
        "{%0,%1,%2,%3}, {%4,%5,%6,%7}, {%8,%9}, {%0,%1,%2,%3};"
        : "+f"(c[0]), "+f"(c[1]), "+f"(c[2]), "+f"(c[3])
        : "r"(a[0]), "r"(a[1]), "r"(a[2]), "r"(a[3]), "r"(b0), "r"(b1));
}

// ---------------- prep: weights -> A-fragment layout, f16 ----------------
__global__ void prep_wAf_kernel(const float* __restrict__ wd) {
    int idx = blockIdx.x * 256 + threadIdx.x;       // b32 index
    if (idx >= NSTEP * 8 * 32 * 4) return;
    int q     = idx & 3;
    int lane  = (idx >> 2) & 31;
    int ot    = (idx >> 7) & 7;
    int step  = idx >> 10;
    int g = lane >> 2, t = lane & 3;
    int row = ot * 16 + g + ((q & 1) << 3);
    int col = step * 16 + t * 2 + ((q >> 1) << 3);
    __half h0 = __float2half_rn(wd[row * RTOT + col]);
    __half h1 = __float2half_rn(wd[row * RTOT + col + 1]);
    g_wAf32[idx] = ((uint32_t)reinterpret_cast<unsigned short&>(h1) << 16)
                 |  (uint32_t)reinterpret_cast<unsigned short&>(h0);
}

// ---------------- main kernel ----------------
__global__ void __launch_bounds__(NTHREADS, 3)
deform_kernel(const float* __restrict__ x,        // [B,C,H,W]
              const float* __restrict__ shape,    // [B,2,H,W]
              const float* __restrict__ w_offset, // [72][2]
              float* __restrict__ out)            // [B,COUT,H,W]
{
    extern __shared__ char smem[];
    const uint32_t smem_u32 = smem_to_u32(smem);
    float* ss0 = (float*)(smem + OFF_SS0);
    float* ss1 = (float*)(smem + OFF_SS1);
    float* swo = (float*)(smem + OFF_SWO);

    const int tid = threadIdx.x;
    const int wid = tid >> 5;
    const int lid = tid & 31;

    const int b   = blockIdx.x >> 9;
    const int rem = blockIdx.x & 511;
    const int h   = rem >> 2;
    const int w0  = (rem & 3) << 5;

    // ---- stage small tables ----
    if (tid < 32)                     ss0[tid]     = shape[(size_t)(b*2+0)*HW + h*WDIM + w0 + tid];
    else if (tid < 64)                ss1[tid-32]  = shape[(size_t)(b*2+1)*HW + h*WDIM + w0 + (tid-32)];
    else if (tid >= 64 && tid < 208)  swo[tid-64]  = w_offset[tid-64];
    __syncthreads();

    // ---- phase A: sample -> f16 into swizzled S [1152][32] (all 8 warps) ----
    for (int i = tid; i < 36 * TPX; i += NTHREADS) {
        int gk = i >> 5, px = i & 31;
        int g  = gk / 9, k = gk - g * 9;
        int ky = k / 3,  kx = k - ky * 3;
        float s0 = ss0[px], s1 = ss1[px];
        float offy = swo[gk*4 + 0] * s0 + swo[gk*4 + 1] * s1;
        float offx = swo[gk*4 + 2] * s0 + swo[gk*4 + 3] * s1;
        float py  = offy + (float)(ky - 1 + h);
        float pxf = offx + (float)(kx - 1 + w0 + px);
        float y0f = floorf(py), x0f = floorf(pxf);
        float fy = py - y0f, fx = pxf - x0f;
        int y0 = (int)y0f, x0 = (int)x0f;

        float aw[4]; int ai[4];
        #pragma unroll
        for (int t = 0; t < 4; t++) {
            int dy = t >> 1, dx = t & 1;
            int yi = y0 + dy, xi = x0 + dx;
            bool valid = (yi >= 0) && (yi < HDIM) && (xi >= 0) && (xi < WDIM);
            float wy = dy ? fy : 1.0f - fy;
            float wx = dx ? fx : 1.0f - fx;
            int yc = min(max(yi, 0), HDIM - 1);
            int xc = min(max(xi, 0), WDIM - 1);
            aw[t] = valid ? (wy * wx) : 0.0f;
            ai[t] = yc * WDIM + xc;
        }

        const float* xb = x + ((size_t)b * CIN + g * CG) * HW;
        const int r0 = (g * CG) * KTAPS + k;     // r for cg=0; stride 9 per cg
        #pragma unroll 4
        for (int cg = 0; cg < CG; cg++) {
            const float* xc = xb + (size_t)cg * HW;
            float v = aw[0]*xc[ai[0]] + aw[1]*xc[ai[1]] + aw[2]*xc[ai[2]] + aw[3]*xc[ai[3]];
            int r  = r0 + cg * KTAPS;
            *(__half*)(smem + SMEM_S_OFF + s_off(r, px)) = __float2half_rn(v);
        }
    }
    __syncthreads();

    // ---- phase B: 8 warps, each o16 x n32, 2-stage software pipeline ----
    const int ot    = wid;               // o = wid*16 .. +15
    const int bkrow = lid & 15;
    const int bsel  = lid >> 4;

    const uint4* gA = reinterpret_cast<const uint4*>(g_wAf32);

    float acc[4][4];
    #pragma unroll
    for (int a2 = 0; a2 < 4; a2++)
        #pragma unroll
        for (int a3 = 0; a3 < 4; a3++) acc[a2][a3] = 0.0f;

    uint32_t bf0[2][4], bf1[2][4];

    // B-fragment loader for a given step into a chosen buffer
#define LOAD_B(buf, stepv) do {                                                  \
        const int _k = ((stepv) << 4) + bkrow;                                   \
        _Pragma("unroll")                                                        \
        for (int _half = 0; _half < 2; _half++) {                                \
            int _bnchk = (_half << 1) + bsel;                                    \
            int _boff  = (_k << 6) + (((_bnchk ^ ((_k >> 1) & 3))) << 4);        \
            ldsm_x4_trans(buf[_half], smem_u32 + SMEM_S_OFF + (uint32_t)_boff);  \
        }                                                                        \
    } while (0)

#define MMA4(Areg, buf) do {                                                     \
        const uint32_t* _a = (const uint32_t*)&(Areg);                           \
        mma_f16(acc[0], _a, buf[0][0], buf[0][1]);                               \
        mma_f16(acc[1], _a, buf[0][2], buf[0][3]);                               \
        mma_f16(acc[2], _a, buf[1][0], buf[1][1]);                               \
        mma_f16(acc[3], _a, buf[1][2], buf[1][3]);                               \
    } while (0)

    // prologue: stage 0
    uint4 A0 = gA[(ot << 5) + lid];          // step 0
    LOAD_B(bf0, 0);

    for (int s = 0; s < NSTEP; s += 2) {
        // stage s+1 (always valid: s+1 <= 71)
        uint4 A1 = gA[(((s + 1) * 8 + ot) << 5) + lid];
        LOAD_B(bf1, s + 1);

        MMA4(A0, bf0);          // consume stage s (operands long since ready)

        // stage s+2 (guarded)
        uint4 A2 = A1;
        if (s + 2 < NSTEP) {
            A2 = gA[(((s + 2) * 8 + ot) << 5) + lid];
            LOAD_B(bf0, s + 2);
        }

        MMA4(A1, bf1);          // consume stage s+1

        A0 = A2;
    }
#undef LOAD_B
#undef MMA4

    // ---- epilogue: acc -> ReLU -> gmem ----
    const int g = lid >> 2, t = lid & 3;
    #pragma unroll
    for (int j = 0; j < 4; j++) {
        int o  = (wid << 4) + g;
        int px = (j << 3) + (t << 1);
        float* op0 = out + (((size_t)b * COUT + o) << 14) + (h << 7) + w0 + px;
        float* op1 = op0 + ((size_t)8 << 14);   // row o+8
        float2 v0 = { fmaxf(acc[j][0], 0.0f), fmaxf(acc[j][1], 0.0f) };
        float2 v1 = { fmaxf(acc[j][2], 0.0f), fmaxf(acc[j][3], 0.0f) };
        *reinterpret_cast<float2*>(op0) = v0;
        *reinterpret_cast<float2*>(op1) = v1;
    }
}

extern "C" void kernel_launch(void* const* d_in, const int* in_sizes, int n_in,
                              void* d_out, int out_size) {
    const float* x        = (const float*)d_in[0];
    const float* shape    = (const float*)d_in[1];
    const float* w_offset = (const float*)d_in[2];
    const float* w_deform = (const float*)d_in[3];
    float* out = (float*)d_out;

    cudaFuncSetAttribute(deform_kernel,
                         cudaFuncAttributeMaxDynamicSharedMemorySize, SMEM_BYTES);

    prep_wAf_kernel<<<(NSTEP * 8 * 32 * 4 + 255) / 256, 256>>>(w_deform);

    const int nblocks = BATCH * HDIM * (WDIM / TPX);   // 2048
    deform_kernel<<<nblocks, NTHREADS, SMEM_BYTES>>>(x, shape, w_offset, out);
}